// round 7
// baseline (speedup 1.0000x reference)
#include <cuda_runtime.h>
#include <cuda_bf16.h>
#include <math.h>
#include <stdint.h>

#define NN 50000
#define NE 800000
#define NG 256
#define LN2F 0.69314718055994531f

// ---------------- scratch (device globals) ----------------
__device__ float g_h  [NN * 64];
__device__ float g_agg[NN * 64];
__device__ float g_e  [NE * 64];
__device__ float g_sums[NG];
__device__ float g_cnt [NG];
// pre-packed B fragments: 3 layers x 320 frags x 32 lanes (uint4 = {bh01,bh23,bl01,bl23})
__device__ uint4 g_frags[3 * 10240];

typedef unsigned long long u64;

__device__ __forceinline__ u64 pack2(float lo, float hi) {
    u64 r; asm("mov.b64 %0, {%1, %2};" : "=l"(r) : "f"(lo), "f"(hi)); return r;
}
__device__ __forceinline__ void fma2(u64 &d, u64 a, u64 b) {
    asm("fma.rn.f32x2 %0, %1, %2, %0;" : "+l"(d) : "l"(a), "l"(b));
}
__device__ __forceinline__ float hsum2(u64 v) {
    float lo, hi; asm("mov.b64 {%0, %1}, %2;" : "=f"(lo), "=f"(hi) : "l"(v));
    return lo + hi;
}
__device__ __forceinline__ float ssp_f(float x) {
    return fmaxf(x, 0.0f) + __logf(1.0f + __expf(-fabsf(x))) - LN2F;
}
// split two floats into bf16 hi pair + bf16 lo (residual) pair, packed b32 (first arg in low half)
__device__ __forceinline__ void bfsplit2(float a, float b, uint32_t &hi, uint32_t &lo) {
    __nv_bfloat16 ha = __float2bfloat16_rn(a), hb = __float2bfloat16_rn(b);
    hi = (uint32_t)__bfloat16_as_ushort(ha) | ((uint32_t)__bfloat16_as_ushort(hb) << 16);
    __nv_bfloat16 la = __float2bfloat16_rn(a - __bfloat162float(ha));
    __nv_bfloat16 lb = __float2bfloat16_rn(b - __bfloat162float(hb));
    lo = (uint32_t)__bfloat16_as_ushort(la) | ((uint32_t)__bfloat16_as_ushort(lb) << 16);
}

__device__ __forceinline__ void mma_bf16(float* c,
    uint32_t a0, uint32_t a1, uint32_t a2, uint32_t a3, uint32_t b0, uint32_t b1) {
    asm("mma.sync.aligned.m16n8k16.row.col.f32.bf16.bf16.f32 "
        "{%0,%1,%2,%3}, {%4,%5,%6,%7}, {%8,%9}, {%0,%1,%2,%3};"
        : "+f"(c[0]), "+f"(c[1]), "+f"(c[2]), "+f"(c[3])
        : "r"(a0), "r"(a1), "r"(a2), "r"(a3), "r"(b0), "r"(b1));
}

// ---------------- init ----------------
__global__ void k_init_nodes(const int* __restrict__ az, const float* __restrict__ emb) {
    int t = blockIdx.x * blockDim.x + threadIdx.x;
    if (t >= NN * 16) return;
    int n = t >> 4, q = t & 15;
    int z = az[n];
    float4 v = ((const float4*)(emb + (size_t)z * 64))[q];
    ((float4*)(g_h + (size_t)n * 64))[q] = v;
    ((float4*)(g_agg + (size_t)n * 64))[q] = make_float4(0.f, 0.f, 0.f, 0.f);
}

__global__ void k_init_edges(const float* __restrict__ dist) {
    int t = blockIdx.x * blockDim.x + threadIdx.x;
    if (t >= NE * 64) return;
    int e = t >> 6, j = t & 63;
    float d = dist[e];
    float c = (5.0f / 63.0f) * (float)j;
    float df = d - c;
    g_e[t] = __expf(-df * df * (63.0f / 5.0f));
}

__global__ void k_zero_pool() {
    int t = threadIdx.x;
    if (t < NG) { g_sums[t] = 0.f; g_cnt[t] = 0.f; }
}

// ---------------- weight fragment prep ----------------
// Fragment layout (per layer, 320 fragments):
//   [0,192):  W1 [192x128]  (12 ktiles x 16 ntiles)
//   [192,256): W2 [128x64]  (8 x 8)
//   [256,288): P1 [64x64]   (4 x 8)
//   [288,320): P2 [64x64]   (4 x 8)
// For fragment (kst, nt): lane holds B elems (k0,n),(k0+1,n),(k0+8,n),(k0+9,n)
// with n = nt*8 + (lane>>2), k0 = kst*16 + 2*(lane&3).
__global__ void k_prep(const float* __restrict__ eu_w1, const float* __restrict__ eu_w2,
                       const float* __restrict__ pe1_w, const float* __restrict__ pe2_w) {
    int s = blockIdx.x * blockDim.x + threadIdx.x;
    if (s >= 3 * 10240) return;
    int l = s / 10240, r = s % 10240;
    int f = r >> 5, lane = r & 31;
    const float* W; int NT, N, fl;
    if (f < 192)      { W = eu_w1 + (size_t)l * 24576; fl = f;       NT = 16; N = 128; }
    else if (f < 256) { W = eu_w2 + (size_t)l * 8192;  fl = f - 192; NT = 8;  N = 64; }
    else if (f < 288) { W = pe1_w + (size_t)l * 4096;  fl = f - 256; NT = 8;  N = 64; }
    else              { W = pe2_w + (size_t)l * 4096;  fl = f - 288; NT = 8;  N = 64; }
    int nt = fl % NT, kst = fl / NT;
    int n  = nt * 8 + (lane >> 2);
    int k0 = kst * 16 + 2 * (lane & 3);
    float w0 = W[(size_t)k0 * N + n];
    float w1 = W[(size_t)(k0 + 1) * N + n];
    float w2 = W[(size_t)(k0 + 8) * N + n];
    float w3 = W[(size_t)(k0 + 9) * N + n];
    uint32_t h01, l01, h23, l23;
    bfsplit2(w0, w1, h01, l01);
    bfsplit2(w2, w3, h23, l23);
    g_frags[s] = make_uint4(h01, h23, l01, l23);
}

// ---------------- smem layout for k_edge_mma ----------------
#define FRAG_U4   10240                 // 320 frags * 32 lanes
#define SM_BIAS1  (FRAG_U4 * 16)        // 163840 B : b1[128]
#define SM_BIAS2  (SM_BIAS1 + 512)      // b2[64]
#define SM_Q1     (SM_BIAS2 + 256)      // q1[64]
#define SM_Q2     (SM_Q1 + 256)         // q2[64]
#define EDGE_SMEM (SM_Q2 + 256)         // 165120 B

#define FR1 0
#define FR2 (192 * 32)
#define FR3 (256 * 32)
#define FR4 (288 * 32)

// ---------------- the mma.sync edge kernel (M=32 per warp) ----------------
__global__ void __launch_bounds__(256, 1) k_edge_mma(
    int layer, int store_e,
    const int* __restrict__ src, const int* __restrict__ dst,
    const float* __restrict__ b1, const float* __restrict__ b2,
    const float* __restrict__ pb1, const float* __restrict__ pb2)
{
    extern __shared__ char smem[];
    uint4* sm4 = (uint4*)smem;
    const int tid = threadIdx.x;

    // load weight fragments + biases
    {
        const uint4* srcf = g_frags + (size_t)layer * FRAG_U4;
        for (int i = tid; i < FRAG_U4; i += 256) sm4[i] = srcf[i];
        float* sB1 = (float*)(smem + SM_BIAS1);
        float* sB2 = (float*)(smem + SM_BIAS2);
        float* sQ1 = (float*)(smem + SM_Q1);
        float* sQ2 = (float*)(smem + SM_Q2);
        if (tid < 128) sB1[tid] = b1[tid];
        if (tid < 64) { sB2[tid] = b2[tid]; sQ1[tid] = pb1[tid]; sQ2[tid] = pb2[tid]; }
    }
    __syncthreads();

    const float* sB1f = (const float*)(smem + SM_BIAS1);
    const float* sB2f = (const float*)(smem + SM_BIAS2);
    const float* sQ1f = (const float*)(smem + SM_Q1);
    const float* sQ2f = (const float*)(smem + SM_Q2);

    const int wid = tid >> 5, lane = tid & 31;
    const int gr = lane >> 2;            // row group 0..7
    const int t2 = 2 * (lane & 3);       // col pair base

    const int NTILES = NE / 32;          // 25000
    const int wstride = gridDim.x * 8;

    for (int tile = blockIdx.x * 8 + wid; tile < NTILES; tile += wstride) {
        const int base = tile * 32;
        // rows: block b covers rows base+16b+gr (A rows 0-7) and base+16b+gr+8 (rows 8-15)
        int rr[4], is[4], id[4];
        rr[0] = base + gr;      rr[1] = base + gr + 8;
        rr[2] = base + gr + 16; rr[3] = base + gr + 24;
#pragma unroll
        for (int j = 0; j < 4; j++) { is[j] = __ldg(src + rr[j]); id[j] = __ldg(dst + rr[j]); }

        // ============ stage 1: C1[32x128] = [hsrc|hdst|e] @ W1 ============
        float c1[2][16][4];
#pragma unroll
        for (int b = 0; b < 2; b++)
#pragma unroll
            for (int nt = 0; nt < 16; nt++) { c1[b][nt][0] = c1[b][nt][1] = c1[b][nt][2] = c1[b][nt][3] = 0.f; }

#pragma unroll 1
        for (int mat = 0; mat < 3; mat++) {
            const float* rp[4];
            if (mat == 0)      {
#pragma unroll
                for (int j = 0; j < 4; j++) rp[j] = g_h + (size_t)is[j] * 64;
            } else if (mat == 1) {
#pragma unroll
                for (int j = 0; j < 4; j++) rp[j] = g_h + (size_t)id[j] * 64;
            } else {
#pragma unroll
                for (int j = 0; j < 4; j++) rp[j] = g_e + (size_t)rr[j] * 64;
            }
#pragma unroll
            for (int kt = 0; kt < 4; kt++) {
                const int kk = kt * 16;
                uint32_t ah[2][4], al[2][4];
#pragma unroll
                for (int b = 0; b < 2; b++) {
                    float2 x0 = *(const float2*)(rp[2 * b]     + kk + t2);
                    float2 x1 = *(const float2*)(rp[2 * b + 1] + kk + t2);
                    float2 x2 = *(const float2*)(rp[2 * b]     + kk + t2 + 8);
                    float2 x3 = *(const float2*)(rp[2 * b + 1] + kk + t2 + 8);
                    bfsplit2(x0.x, x0.y, ah[b][0], al[b][0]);
                    bfsplit2(x1.x, x1.y, ah[b][1], al[b][1]);
                    bfsplit2(x2.x, x2.y, ah[b][2], al[b][2]);
                    bfsplit2(x3.x, x3.y, ah[b][3], al[b][3]);
                }
                const uint4* fp = sm4 + FR1 + (size_t)(mat * 4 + kt) * 16 * 32 + lane;
#pragma unroll
                for (int nt = 0; nt < 16; nt++) {
                    uint4 f = fp[nt * 32];
#pragma unroll
                    for (int b = 0; b < 2; b++) {
                        mma_bf16(c1[b][nt], ah[b][0], ah[b][1], ah[b][2], ah[b][3], f.x, f.y);
                        mma_bf16(c1[b][nt], al[b][0], al[b][1], al[b][2], al[b][3], f.x, f.y);
                        mma_bf16(c1[b][nt], ah[b][0], ah[b][1], ah[b][2], ah[b][3], f.z, f.w);
                    }
                }
            }
        }

        // ============ epi1+stage2 interleaved per kt: C2 = ssp(C1+b1) @ W2 ============
        float c2[2][8][4];
#pragma unroll
        for (int b = 0; b < 2; b++)
#pragma unroll
            for (int nt = 0; nt < 8; nt++) { c2[b][nt][0] = c2[b][nt][1] = c2[b][nt][2] = c2[b][nt][3] = 0.f; }
#pragma unroll 1
        for (int kt = 0; kt < 8; kt++) {
            uint32_t a2h[2][4], a2l[2][4];
#pragma unroll
            for (int b = 0; b < 2; b++) {
#pragma unroll
                for (int half = 0; half < 2; half++) {
                    int nt = 2 * kt + half;
                    float2 bb = *(const float2*)(sB1f + nt * 8 + t2);
                    float v0 = ssp_f(c1[b][nt][0] + bb.x), v1 = ssp_f(c1[b][nt][1] + bb.y);
                    float v2 = ssp_f(c1[b][nt][2] + bb.x), v3 = ssp_f(c1[b][nt][3] + bb.y);
                    bfsplit2(v0, v1, a2h[b][2 * half],     a2l[b][2 * half]);
                    bfsplit2(v2, v3, a2h[b][2 * half + 1], a2l[b][2 * half + 1]);
                }
            }
            const uint4* fp = sm4 + FR2 + (size_t)kt * 8 * 32 + lane;
#pragma unroll
            for (int nt = 0; nt < 8; nt++) {
                uint4 f = fp[nt * 32];
#pragma unroll
                for (int b = 0; b < 2; b++) {
                    mma_bf16(c2[b][nt], a2h[b][0], a2h[b][1], a2h[b][2], a2h[b][3], f.x, f.y);
                    mma_bf16(c2[b][nt], a2l[b][0], a2l[b][1], a2l[b][2], a2l[b][3], f.x, f.y);
                    mma_bf16(c2[b][nt], a2h[b][0], a2h[b][1], a2h[b][2], a2h[b][3], f.z, f.w);
                }
            }
        }

        // ============ epi2+stage3 interleaved: C3 = (C2+b2) @ P1 ; e' -> g_e ============
        float c3[2][8][4];
#pragma unroll
        for (int b = 0; b < 2; b++)
#pragma unroll
            for (int nt = 0; nt < 8; nt++) { c3[b][nt][0] = c3[b][nt][1] = c3[b][nt][2] = c3[b][nt][3] = 0.f; }
#pragma unroll 1
        for (int kt = 0; kt < 4; kt++) {
            uint32_t a3h[2][4], a3l[2][4];
#pragma unroll
            for (int b = 0; b < 2; b++) {
#pragma unroll
                for (int half = 0; half < 2; half++) {
                    int nt = 2 * kt + half;
                    float2 bb = *(const float2*)(sB2f + nt * 8 + t2);
                    float x0 = c2[b][nt][0] + bb.x, x1 = c2[b][nt][1] + bb.y;
                    float x2 = c2[b][nt][2] + bb.x, x3 = c2[b][nt][3] + bb.y;
                    if (store_e) {
                        *(float2*)(g_e + (size_t)rr[2 * b]     * 64 + nt * 8 + t2) = make_float2(x0, x1);
                        *(float2*)(g_e + (size_t)rr[2 * b + 1] * 64 + nt * 8 + t2) = make_float2(x2, x3);
                    }
                    bfsplit2(x0, x1, a3h[b][2 * half],     a3l[b][2 * half]);
                    bfsplit2(x2, x3, a3h[b][2 * half + 1], a3l[b][2 * half + 1]);
                }
            }
            const uint4* fp = sm4 + FR3 + (size_t)kt * 8 * 32 + lane;
#pragma unroll
            for (int nt = 0; nt < 8; nt++) {
                uint4 f = fp[nt * 32];
#pragma unroll
                for (int b = 0; b < 2; b++) {
                    mma_bf16(c3[b][nt], a3h[b][0], a3h[b][1], a3h[b][2], a3h[b][3], f.x, f.y);
                    mma_bf16(c3[b][nt], a3l[b][0], a3l[b][1], a3l[b][2], a3l[b][3], f.x, f.y);
                    mma_bf16(c3[b][nt], a3h[b][0], a3h[b][1], a3h[b][2], a3h[b][3], f.z, f.w);
                }
            }
        }

        // ============ epi3+stage4 interleaved: C4 = ssp(C3+q1) @ P2 ============
        float c4[2][8][4];
#pragma unroll
        for (int b = 0; b < 2; b++)
#pragma unroll
            for (int nt = 0; nt < 8; nt++) { c4[b][nt][0] = c4[b][nt][1] = c4[b][nt][2] = c4[b][nt][3] = 0.f; }
#pragma unroll 1
        for (int kt = 0; kt < 4; kt++) {
            uint32_t a4h[2][4], a4l[2][4];
#pragma unroll
            for (int b = 0; b < 2; b++) {
#pragma unroll
                for (int half = 0; half < 2; half++) {
                    int nt = 2 * kt + half;
                    float2 bb = *(const float2*)(sQ1f + nt * 8 + t2);
                    float v0 = ssp_f(c3[b][nt][0] + bb.x), v1 = ssp_f(c3[b][nt][1] + bb.y);
                    float v2 = ssp_f(c3[b][nt][2] + bb.x), v3 = ssp_f(c3[b][nt][3] + bb.y);
                    bfsplit2(v0, v1, a4h[b][2 * half],     a4l[b][2 * half]);
                    bfsplit2(v2, v3, a4h[b][2 * half + 1], a4l[b][2 * half + 1]);
                }
            }
            const uint4* fp = sm4 + FR4 + (size_t)kt * 8 * 32 + lane;
#pragma unroll
            for (int nt = 0; nt < 8; nt++) {
                uint4 f = fp[nt * 32];
#pragma unroll
                for (int b = 0; b < 2; b++) {
                    mma_bf16(c4[b][nt], a4h[b][0], a4h[b][1], a4h[b][2], a4h[b][3], f.x, f.y);
                    mma_bf16(c4[b][nt], a4l[b][0], a4l[b][1], a4l[b][2], a4l[b][3], f.x, f.y);
                    mma_bf16(c4[b][nt], a4h[b][0], a4h[b][1], a4h[b][2], a4h[b][3], f.z, f.w);
                }
            }
        }

        // ============ epi 4: he = C4 + q2; scatter-add to g_agg[dst] ============
#pragma unroll
        for (int b = 0; b < 2; b++) {
            float* da = g_agg + (size_t)id[2 * b]     * 64;
            float* db = g_agg + (size_t)id[2 * b + 1] * 64;
#pragma unroll
            for (int nt = 0; nt < 8; nt++) {
                float2 bb = *(const float2*)(sQ2f + nt * 8 + t2);
                float x0 = c4[b][nt][0] + bb.x, x1 = c4[b][nt][1] + bb.y;
                float x2 = c4[b][nt][2] + bb.x, x3 = c4[b][nt][3] + bb.y;
                asm volatile("red.global.add.v2.f32 [%0], {%1, %2};"
                             :: "l"(da + nt * 8 + t2), "f"(x0), "f"(x1) : "memory");
                asm volatile("red.global.add.v2.f32 [%0], {%1, %2};"
                             :: "l"(db + nt * 8 + t2), "f"(x2), "f"(x3) : "memory");
            }
        }
    }
}

// ---------------- node update: h += ssp(agg@A+ba)@B + bb; agg=0 ----------------
#define UPD_SMEM_FLOATS 12928
__global__ void __launch_bounds__(512, 1) k_update(
    const float* __restrict__ wa, const float* __restrict__ ba,
    const float* __restrict__ wb, const float* __restrict__ bb_)
{
    extern __shared__ float sm[];
    float* sAT = sm;
    float* sBT = sm + 4352;
    float* sBa = sm + 8704;
    float* sBb = sm + 8768;
    float* sScr = sm + 8832;
    int tid = threadIdx.x;
    for (int i = tid; i < 4096; i += 512) {
        int k = i >> 6, c = i & 63;
        sAT[c * 68 + k] = wa[i];
        sBT[c * 68 + k] = wb[i];
    }
    if (tid < 64) { sBa[tid] = ba[tid]; sBb[tid] = bb_[tid]; }
    __syncthreads();

    int lane = tid & 31, warp = tid >> 5;
    float* scrN = sScr + warp * 256;
    const float bav0 = sBa[lane], bav1 = sBa[lane + 32];
    const float bbv0 = sBb[lane], bbv1 = sBb[lane + 32];
    const float* a0p = sAT + lane * 68;
    const float* a1p = sAT + (lane + 32) * 68;
    const float* b0p = sBT + lane * 68;
    const float* b1p = sBT + (lane + 32) * 68;
    const int stride = gridDim.x * 16;

    for (int g = blockIdx.x * 16 + warp; g < NN / 4; g += stride) {
        int n0 = g * 4;
        float4* av = (float4*)(g_agg + (size_t)n0 * 64);
        float4 z = make_float4(0.f, 0.f, 0.f, 0.f);
        float4 t0 = av[lane], t1v = av[lane + 32];
        ((float4*)scrN)[lane] = t0; ((float4*)scrN)[lane + 32] = t1v;
        av[lane] = z; av[lane + 32] = z;
        __syncwarp();
        u64 aa[4][2];
#pragma unroll
        for (int i = 0; i < 4; i++) { aa[i][0] = pack2(bav0, 0.f); aa[i][1] = pack2(bav1, 0.f); }
#pragma unroll 4
        for (int k = 0; k < 64; k += 4) {
            ulonglong2 w0 = *(const ulonglong2*)(a0p + k);
            ulonglong2 w1 = *(const ulonglong2*)(a1p + k);
#pragma unroll
            for (int i = 0; i < 4; i++) {
                ulonglong2 tt = *(const ulonglong2*)(scrN + i * 64 + k);
                fma2(aa[i][0], tt.x, w0.x); fma2(aa[i][0], tt.y, w0.y);
                fma2(aa[i][1], tt.x, w1.x); fma2(aa[i][1], tt.y, w1.y);
            }
        }
        __syncwarp();
#pragma unroll
        for (int i = 0; i < 4; i++) {
            scrN[i * 64 + lane]      = ssp_f(hsum2(aa[i][0]));
            scrN[i * 64 + lane + 32] = ssp_f(hsum2(aa[i][1]));
        }
        __syncwarp();
        u64 oo[4][2];
#pragma unroll
        for (int i = 0; i < 4; i++) { oo[i][0] = pack2(bbv0, 0.f); oo[i][1] = pack2(bbv1, 0.f); }
#pragma unroll 4
        for (int k = 0; k < 64; k += 4) {
            ulonglong2 w0 = *(const ulonglong2*)(b0p + k);
            ulonglong2 w1 = *(const ulonglong2*)(b1p + k);
#pragma unroll
            for (int i = 0; i < 4; i++) {
                ulonglong2 tt = *(const ulonglong2*)(scrN + i * 64 + k);
                fma2(oo[i][0], tt.x, w0.x); fma2(oo[i][0], tt.y, w0.y);
                fma2(oo[i][1], tt.x, w1.x); fma2(oo[i][1], tt.y, w1.y);
            }
        }
        __syncwarp();
#pragma unroll
        for (int i = 0; i < 4; i++) {
            float* hp = g_h + (size_t)(n0 + i) * 64;
            hp[lane]      += hsum2(oo[i][0]);
            hp[lane + 32] += hsum2(oo[i][1]);
        }
        __syncwarp();
    }
}

// ---------------- readout + per-graph mean ----------------
__global__ void __launch_bounds__(256) k_readout(
    const int* __restrict__ gid,
    const float* __restrict__ d1w, const float* __restrict__ d1b,
    const float* __restrict__ d2w, const float* __restrict__ d2b)
{
    __shared__ float sW[2048], sB1r[32], sW2r[32];
    __shared__ float sB2r;
    int tid = threadIdx.x;
    for (int i = tid; i < 2048; i += 256) sW[i] = d1w[i];
    if (tid < 32) { sB1r[tid] = d1b[tid]; sW2r[tid] = d2w[tid]; }
    if (tid == 0) sB2r = d2b[0];
    __syncthreads();
    int lane = tid & 31, warp = tid >> 5;
    int nw = gridDim.x * 8;
    for (int n = blockIdx.x * 8 + warp; n < NN; n += nw) {
        float2 hv = *(const float2*)(g_h + (size_t)n * 64 + 2 * lane);
        float a = sB1r[lane];
#pragma unroll 8
        for (int k = 0; k < 64; k++) {
            float ek = __shfl_sync(0xffffffffu, (k & 1) ? hv.y : hv.x, k >> 1);
            a = fmaf(ek, sW[k * 32 + lane], a);
        }
        float p = ssp_f(a) * sW2r[lane];
#pragma unroll
        for (int off = 16; off; off >>= 1) p += __shfl_xor_sync(0xffffffffu, p, off);
        if (lane == 0) {
            int g = gid[n];
            atomicAdd(&g_sums[g], p + sB2r);
            atomicAdd(&g_cnt[g], 1.0f);
        }
    }
}

__global__ void k_final(float* __restrict__ out) {
    int t = threadIdx.x;
    if (t < NG) out[t] = g_sums[t] / fmaxf(g_cnt[t], 1.0f);
}

// ---------------- launch ----------------
extern "C" void kernel_launch(void* const* d_in, const int* in_sizes, int n_in,
                              void* d_out, int out_size) {
    const int*   az     = (const int*)d_in[0];
    const float* dist   = (const float*)d_in[1];
    const int*   src    = (const int*)d_in[2];
    const int*   dst    = (const int*)d_in[3];
    const int*   gid    = (const int*)d_in[4];
    const float* emb    = (const float*)d_in[5];
    const float* eu_w1  = (const float*)d_in[6];
    const float* eu_b1  = (const float*)d_in[7];
    const float* eu_w2  = (const float*)d_in[8];
    const float* eu_b2  = (const float*)d_in[9];
    const float* pe1_w  = (const float*)d_in[10];
    const float* pe1_b  = (const float*)d_in[11];
    const float* pe2_w  = (const float*)d_in[12];
    const float* pe2_b  = (const float*)d_in[13];
    const float* pn2a_w = (const float*)d_in[14];
    const float* pn2a_b = (const float*)d_in[15];
    const float* pn2b_w = (const float*)d_in[16];
    const float* pn2b_b = (const float*)d_in[17];
    const float* d1w    = (const float*)d_in[18];
    const float* d1b    = (const float*)d_in[19];
    const float* d2w    = (const float*)d_in[20];
    const float* d2b    = (const float*)d_in[21];

    cudaFuncSetAttribute(k_edge_mma, cudaFuncAttributeMaxDynamicSharedMemorySize, EDGE_SMEM);
    cudaFuncSetAttribute(k_update,   cudaFuncAttributeMaxDynamicSharedMemorySize, UPD_SMEM_FLOATS * 4);

    k_init_nodes<<<(NN * 16 + 255) / 256, 256>>>(az, emb);
    k_init_edges<<<(NE * 64 + 255) / 256, 256>>>(dist);
    k_zero_pool<<<1, 256>>>();
    k_prep<<<(3 * 10240 + 255) / 256, 256>>>(eu_w1, eu_w2, pe1_w, pe2_w);

    for (int l = 0; l < 3; l++) {
        k_edge_mma<<<148, 256, EDGE_SMEM>>>(
            l, (l < 2) ? 1 : 0, src, dst,
            eu_b1 + l * 128, eu_b2 + l * 64,
            pe1_b + l * 64,  pe2_b + l * 64);
        k_update<<<148, 512, UPD_SMEM_FLOATS * 4>>>(
            pn2a_w + (size_t)l * 4096, pn2a_b + l * 64,
            pn2b_w + (size_t)l * 4096, pn2b_b + l * 64);
    }
    k_readout<<<296, 256>>>(gid, d1w, d1b, d2w, d2b);
    k_final<<<1, 256>>>((float*)d_out);
}

// round 8
// speedup vs baseline: 1.6936x; 1.6936x over previous
#include <cuda_runtime.h>
#include <cuda_bf16.h>
#include <math.h>
#include <stdint.h>

#define NN 50000
#define NE 800000
#define NG 256
#define LN2F 0.69314718055994531f

// ---------------- scratch (device globals) ----------------
__device__ float g_h  [NN * 64];
__device__ float g_agg[NN * 64];
__device__ float g_sums[NG];
__device__ float g_cnt [NG];
// split-planar bf16 activations, A-fragment slot layout:
//   per row: 16 hi u64 slots + 16 lo u64 slots (256B).
//   slot s = 4*kt + q  holds bf16x2 pairs for cols (16kt+2q, +1) [.x] and (16kt+2q+8, +9) [.y]
__device__ uint2 g_ebf[(size_t)NE * 32];
__device__ uint2 g_hbf[(size_t)NN * 32];
// pre-packed B fragments: 3 layers x 320 frags x 32 lanes (uint4 = {bh01,bh23,bl01,bl23})
__device__ uint4 g_frags[3 * 10240];

typedef unsigned long long u64;

__device__ __forceinline__ u64 pack2(float lo, float hi) {
    u64 r; asm("mov.b64 %0, {%1, %2};" : "=l"(r) : "f"(lo), "f"(hi)); return r;
}
__device__ __forceinline__ void fma2(u64 &d, u64 a, u64 b) {
    asm("fma.rn.f32x2 %0, %1, %2, %0;" : "+l"(d) : "l"(a), "l"(b));
}
__device__ __forceinline__ float hsum2(u64 v) {
    float lo, hi; asm("mov.b64 {%0, %1}, %2;" : "=f"(lo), "=f"(hi) : "l"(v));
    return lo + hi;
}
__device__ __forceinline__ float ssp_f(float x) {
    return fmaxf(x, 0.0f) + __logf(1.0f + __expf(-fabsf(x))) - LN2F;
}
// split two floats into bf16 hi pair + bf16 lo (residual) pair, packed b32 (first arg low half)
__device__ __forceinline__ void bfsplit2(float a, float b, uint32_t &hi, uint32_t &lo) {
    __nv_bfloat16 ha = __float2bfloat16_rn(a), hb = __float2bfloat16_rn(b);
    hi = (uint32_t)__bfloat16_as_ushort(ha) | ((uint32_t)__bfloat16_as_ushort(hb) << 16);
    __nv_bfloat16 la = __float2bfloat16_rn(a - __bfloat162float(ha));
    __nv_bfloat16 lb = __float2bfloat16_rn(b - __bfloat162float(hb));
    lo = (uint32_t)__bfloat16_as_ushort(la) | ((uint32_t)__bfloat16_as_ushort(lb) << 16);
}

__device__ __forceinline__ void mma_bf16(float* c,
    uint32_t a0, uint32_t a1, uint32_t a2, uint32_t a3, uint32_t b0, uint32_t b1) {
    asm("mma.sync.aligned.m16n8k16.row.col.f32.bf16.bf16.f32 "
        "{%0,%1,%2,%3}, {%4,%5,%6,%7}, {%8,%9}, {%0,%1,%2,%3};"
        : "+f"(c[0]), "+f"(c[1]), "+f"(c[2]), "+f"(c[3])
        : "r"(a0), "r"(a1), "r"(a2), "r"(a3), "r"(b0), "r"(b1));
}

// ---------------- init ----------------
__global__ void k_init_nodes(const int* __restrict__ az, const float* __restrict__ emb) {
    int t = blockIdx.x * blockDim.x + threadIdx.x;
    if (t >= NN * 16) return;
    int n = t >> 4, q = t & 15;
    int z = az[n];
    float4 v = ((const float4*)(emb + (size_t)z * 64))[q];
    ((float4*)(g_h + (size_t)n * 64))[q] = v;
    ((float4*)(g_agg + (size_t)n * 64))[q] = make_float4(0.f, 0.f, 0.f, 0.f);
}

// build split-planar bf16 copy of g_h
__global__ void k_h2bf() {
    int t = blockIdx.x * blockDim.x + threadIdx.x;
    if (t >= NN * 16) return;
    int n = t >> 4, s = t & 15;
    int kt = s >> 2, q = s & 3;
    int k1 = 16 * kt + 2 * q;
    const float* hp = g_h + (size_t)n * 64;
    uint32_t h0, l0, h1, l1;
    bfsplit2(hp[k1],     hp[k1 + 1], h0, l0);
    bfsplit2(hp[k1 + 8], hp[k1 + 9], h1, l1);
    g_hbf[(size_t)n * 32 + s]      = make_uint2(h0, h1);
    g_hbf[(size_t)n * 32 + 16 + s] = make_uint2(l0, l1);
}

__global__ void k_init_edges(const float* __restrict__ dist) {
    int t = blockIdx.x * blockDim.x + threadIdx.x;
    if (t >= NE * 16) return;
    int e = t >> 4, s = t & 15;
    int kt = s >> 2, q = s & 3;
    int k1 = 16 * kt + 2 * q;
    float d = dist[e];
    const float gap = 63.0f / 5.0f, step = 5.0f / 63.0f;
    float v0, v1, v2, v3;
    { float df = d - step * (float)(k1);     v0 = __expf(-df * df * gap); }
    { float df = d - step * (float)(k1 + 1); v1 = __expf(-df * df * gap); }
    { float df = d - step * (float)(k1 + 8); v2 = __expf(-df * df * gap); }
    { float df = d - step * (float)(k1 + 9); v3 = __expf(-df * df * gap); }
    uint32_t h0, l0, h1, l1;
    bfsplit2(v0, v1, h0, l0);
    bfsplit2(v2, v3, h1, l1);
    g_ebf[(size_t)e * 32 + s]      = make_uint2(h0, h1);
    g_ebf[(size_t)e * 32 + 16 + s] = make_uint2(l0, l1);
}

__global__ void k_zero_pool() {
    int t = threadIdx.x;
    if (t < NG) { g_sums[t] = 0.f; g_cnt[t] = 0.f; }
}

// ---------------- weight fragment prep ----------------
// Fragment layout (per layer, 320 fragments):
//   [0,192):  W1 [192x128]  (12 ktiles x 16 ntiles)
//   [192,256): W2 [128x64]  (8 x 8)
//   [256,288): P1 [64x64]   (4 x 8)
//   [288,320): P2 [64x64]   (4 x 8)
__global__ void k_prep(const float* __restrict__ eu_w1, const float* __restrict__ eu_w2,
                       const float* __restrict__ pe1_w, const float* __restrict__ pe2_w) {
    int s = blockIdx.x * blockDim.x + threadIdx.x;
    if (s >= 3 * 10240) return;
    int l = s / 10240, r = s % 10240;
    int f = r >> 5, lane = r & 31;
    const float* W; int NT, N, fl;
    if (f < 192)      { W = eu_w1 + (size_t)l * 24576; fl = f;       NT = 16; N = 128; }
    else if (f < 256) { W = eu_w2 + (size_t)l * 8192;  fl = f - 192; NT = 8;  N = 64; }
    else if (f < 288) { W = pe1_w + (size_t)l * 4096;  fl = f - 256; NT = 8;  N = 64; }
    else              { W = pe2_w + (size_t)l * 4096;  fl = f - 288; NT = 8;  N = 64; }
    int nt = fl % NT, kst = fl / NT;
    int n  = nt * 8 + (lane >> 2);
    int k0 = kst * 16 + 2 * (lane & 3);
    float w0 = W[(size_t)k0 * N + n];
    float w1 = W[(size_t)(k0 + 1) * N + n];
    float w2 = W[(size_t)(k0 + 8) * N + n];
    float w3 = W[(size_t)(k0 + 9) * N + n];
    uint32_t h01, l01, h23, l23;
    bfsplit2(w0, w1, h01, l01);
    bfsplit2(w2, w3, h23, l23);
    g_frags[s] = make_uint4(h01, h23, l01, l23);
}

// ---------------- smem layout for k_edge_mma ----------------
#define FRAG_U4   10240                 // 320 frags * 32 lanes
#define SM_BIAS1  (FRAG_U4 * 16)        // 163840 B : b1[128]
#define SM_BIAS2  (SM_BIAS1 + 512)      // b2[64]
#define SM_Q1     (SM_BIAS2 + 256)      // q1[64]
#define SM_Q2     (SM_Q1 + 256)         // q2[64]
#define EDGE_SMEM (SM_Q2 + 256)         // 165120 B

#define FR1 0
#define FR2 (192 * 32)
#define FR3 (256 * 32)
#define FR4 (288 * 32)

// ---------------- the mma.sync edge kernel (M=16/warp, 384 thr, split-planar acts) ----------------
__global__ void __launch_bounds__(384, 1) k_edge_mma(
    int layer, int store_e,
    const int* __restrict__ src, const int* __restrict__ dst,
    const float* __restrict__ b1, const float* __restrict__ b2,
    const float* __restrict__ pb1, const float* __restrict__ pb2)
{
    extern __shared__ char smem[];
    uint4* sm4 = (uint4*)smem;
    const int tid = threadIdx.x;

    // load weight fragments + biases
    {
        const uint4* srcf = g_frags + (size_t)layer * FRAG_U4;
        for (int i = tid; i < FRAG_U4; i += 384) sm4[i] = srcf[i];
        float* sB1 = (float*)(smem + SM_BIAS1);
        float* sB2 = (float*)(smem + SM_BIAS2);
        float* sQ1 = (float*)(smem + SM_Q1);
        float* sQ2 = (float*)(smem + SM_Q2);
        if (tid < 128) sB1[tid] = b1[tid];
        if (tid < 64) { sB2[tid] = b2[tid]; sQ1[tid] = pb1[tid]; sQ2[tid] = pb2[tid]; }
    }
    __syncthreads();

    const float* sB1f = (const float*)(smem + SM_BIAS1);
    const float* sB2f = (const float*)(smem + SM_BIAS2);
    const float* sQ1f = (const float*)(smem + SM_Q1);
    const float* sQ2f = (const float*)(smem + SM_Q2);

    const int wid = tid >> 5, lane = tid & 31;
    const int gr = lane >> 2;            // row group 0..7
    const int q  = lane & 3;
    const int t2 = 2 * q;                // col pair base

    const int NTILES = NE / 16;          // 50000
    const int wstride = gridDim.x * 12;

    for (int tile = blockIdx.x * 12 + wid; tile < NTILES; tile += wstride) {
        const int base = tile * 16;
        const int r0 = base + gr, r1 = base + gr + 8;
        const int is0 = __ldg(src + r0), is8 = __ldg(src + r1);
        const int id0 = __ldg(dst + r0), id8 = __ldg(dst + r1);

        // ============ stage 1: C1[16x128] = [hsrc|hdst|e] @ W1 ============
        float c1[16][4];
#pragma unroll
        for (int nt = 0; nt < 16; nt++) { c1[nt][0] = c1[nt][1] = c1[nt][2] = c1[nt][3] = 0.f; }

#pragma unroll 1
        for (int mat = 0; mat < 3; mat++) {
            const uint2 *pa, *pb;
            if (mat == 0)      { pa = g_hbf + (size_t)is0 * 32; pb = g_hbf + (size_t)is8 * 32; }
            else if (mat == 1) { pa = g_hbf + (size_t)id0 * 32; pb = g_hbf + (size_t)id8 * 32; }
            else               { pa = g_ebf + (size_t)r0 * 32;  pb = g_ebf + (size_t)r1 * 32; }
#pragma unroll
            for (int kt = 0; kt < 4; kt++) {
                uint2 h0 = __ldg(pa + 4 * kt + q);
                uint2 h1 = __ldg(pb + 4 * kt + q);
                uint2 l0 = __ldg(pa + 16 + 4 * kt + q);
                uint2 l1 = __ldg(pb + 16 + 4 * kt + q);
                const uint4* fp = sm4 + FR1 + (size_t)(mat * 4 + kt) * 16 * 32 + lane;
#pragma unroll
                for (int nt = 0; nt < 16; nt++) {
                    uint4 f = fp[nt * 32];
                    mma_bf16(c1[nt], h0.x, h1.x, h0.y, h1.y, f.x, f.y);
                    mma_bf16(c1[nt], l0.x, l1.x, l0.y, l1.y, f.x, f.y);
                    mma_bf16(c1[nt], h0.x, h1.x, h0.y, h1.y, f.z, f.w);
                }
            }
        }

        // ============ epi1+stage2 interleaved per kt: C2 = ssp(C1+b1) @ W2 ============
        float c2[8][4];
#pragma unroll
        for (int nt = 0; nt < 8; nt++) { c2[nt][0] = c2[nt][1] = c2[nt][2] = c2[nt][3] = 0.f; }
#pragma unroll 1
        for (int kt = 0; kt < 8; kt++) {
            uint32_t a2h[4], a2l[4];
#pragma unroll
            for (int half = 0; half < 2; half++) {
                int nt = 2 * kt + half;
                float2 bb = *(const float2*)(sB1f + nt * 8 + t2);
                float v0 = ssp_f(c1[nt][0] + bb.x), v1 = ssp_f(c1[nt][1] + bb.y);
                float v2 = ssp_f(c1[nt][2] + bb.x), v3 = ssp_f(c1[nt][3] + bb.y);
                bfsplit2(v0, v1, a2h[2 * half],     a2l[2 * half]);
                bfsplit2(v2, v3, a2h[2 * half + 1], a2l[2 * half + 1]);
            }
            const uint4* fp = sm4 + FR2 + (size_t)kt * 8 * 32 + lane;
#pragma unroll
            for (int nt = 0; nt < 8; nt++) {
                uint4 f = fp[nt * 32];
                mma_bf16(c2[nt], a2h[0], a2h[1], a2h[2], a2h[3], f.x, f.y);
                mma_bf16(c2[nt], a2l[0], a2l[1], a2l[2], a2l[3], f.x, f.y);
                mma_bf16(c2[nt], a2h[0], a2h[1], a2h[2], a2h[3], f.z, f.w);
            }
        }

        // ============ epi2+stage3 interleaved: C3 = (C2+b2) @ P1 ; e' -> g_ebf ============
        float c3[8][4];
#pragma unroll
        for (int nt = 0; nt < 8; nt++) { c3[nt][0] = c3[nt][1] = c3[nt][2] = c3[nt][3] = 0.f; }
#pragma unroll 1
        for (int kt = 0; kt < 4; kt++) {
            uint32_t a3h[4], a3l[4];
#pragma unroll
            for (int half = 0; half < 2; half++) {
                int nt = 2 * kt + half;
                float2 bb = *(const float2*)(sB2f + nt * 8 + t2);
                float x0 = c2[nt][0] + bb.x, x1 = c2[nt][1] + bb.y;
                float x2 = c2[nt][2] + bb.x, x3 = c2[nt][3] + bb.y;
                bfsplit2(x0, x1, a3h[2 * half],     a3l[2 * half]);
                bfsplit2(x2, x3, a3h[2 * half + 1], a3l[2 * half + 1]);
            }
            if (store_e) {
                // fragment regs are exactly the slot pairs: [0]=row0 half0, [2]=row0 half1, etc.
                uint2* pe0 = g_ebf + (size_t)r0 * 32;
                uint2* pe1 = g_ebf + (size_t)r1 * 32;
                pe0[4 * kt + q]      = make_uint2(a3h[0], a3h[2]);
                pe1[4 * kt + q]      = make_uint2(a3h[1], a3h[3]);
                pe0[16 + 4 * kt + q] = make_uint2(a3l[0], a3l[2]);
                pe1[16 + 4 * kt + q] = make_uint2(a3l[1], a3l[3]);
            }
            const uint4* fp = sm4 + FR3 + (size_t)kt * 8 * 32 + lane;
#pragma unroll
            for (int nt = 0; nt < 8; nt++) {
                uint4 f = fp[nt * 32];
                mma_bf16(c3[nt], a3h[0], a3h[1], a3h[2], a3h[3], f.x, f.y);
                mma_bf16(c3[nt], a3l[0], a3l[1], a3l[2], a3l[3], f.x, f.y);
                mma_bf16(c3[nt], a3h[0], a3h[1], a3h[2], a3h[3], f.z, f.w);
            }
        }

        // ============ epi3+stage4 interleaved: C4 = ssp(C3+q1) @ P2 ============
        float c4[8][4];
#pragma unroll
        for (int nt = 0; nt < 8; nt++) { c4[nt][0] = c4[nt][1] = c4[nt][2] = c4[nt][3] = 0.f; }
#pragma unroll 1
        for (int kt = 0; kt < 4; kt++) {
            uint32_t a4h[4], a4l[4];
#pragma unroll
            for (int half = 0; half < 2; half++) {
                int nt = 2 * kt + half;
                float2 bb = *(const float2*)(sQ1f + nt * 8 + t2);
                float v0 = ssp_f(c3[nt][0] + bb.x), v1 = ssp_f(c3[nt][1] + bb.y);
                float v2 = ssp_f(c3[nt][2] + bb.x), v3 = ssp_f(c3[nt][3] + bb.y);
                bfsplit2(v0, v1, a4h[2 * half],     a4l[2 * half]);
                bfsplit2(v2, v3, a4h[2 * half + 1], a4l[2 * half + 1]);
            }
            const uint4* fp = sm4 + FR4 + (size_t)kt * 8 * 32 + lane;
#pragma unroll
            for (int nt = 0; nt < 8; nt++) {
                uint4 f = fp[nt * 32];
                mma_bf16(c4[nt], a4h[0], a4h[1], a4h[2], a4h[3], f.x, f.y);
                mma_bf16(c4[nt], a4l[0], a4l[1], a4l[2], a4l[3], f.x, f.y);
                mma_bf16(c4[nt], a4h[0], a4h[1], a4h[2], a4h[3], f.z, f.w);
            }
        }

        // ============ epi 4: he = C4 + q2; scatter-add to g_agg[dst] ============
        {
            float* da = g_agg + (size_t)id0 * 64;
            float* db = g_agg + (size_t)id8 * 64;
#pragma unroll
            for (int nt = 0; nt < 8; nt++) {
                float2 bb = *(const float2*)(sQ2f + nt * 8 + t2);
                float x0 = c4[nt][0] + bb.x, x1 = c4[nt][1] + bb.y;
                float x2 = c4[nt][2] + bb.x, x3 = c4[nt][3] + bb.y;
                asm volatile("red.global.add.v2.f32 [%0], {%1, %2};"
                             :: "l"(da + nt * 8 + t2), "f"(x0), "f"(x1) : "memory");
                asm volatile("red.global.add.v2.f32 [%0], {%1, %2};"
                             :: "l"(db + nt * 8 + t2), "f"(x2), "f"(x3) : "memory");
            }
        }
    }
}

// ---------------- node update: h += ssp(agg@A+ba)@B + bb; agg=0; refresh g_hbf ----------------
#define UPD_SMEM_FLOATS 12928
__global__ void __launch_bounds__(512, 1) k_update(
    const float* __restrict__ wa, const float* __restrict__ ba,
    const float* __restrict__ wb, const float* __restrict__ bb_,
    int write_bf)
{
    extern __shared__ float sm[];
    float* sAT = sm;
    float* sBT = sm + 4352;
    float* sBa = sm + 8704;
    float* sBb = sm + 8768;
    float* sScr = sm + 8832;
    int tid = threadIdx.x;
    for (int i = tid; i < 4096; i += 512) {
        int k = i >> 6, c = i & 63;
        sAT[c * 68 + k] = wa[i];
        sBT[c * 68 + k] = wb[i];
    }
    if (tid < 64) { sBa[tid] = ba[tid]; sBb[tid] = bb_[tid]; }
    __syncthreads();

    int lane = tid & 31, warp = tid >> 5;
    float* scrN = sScr + warp * 256;
    const float bav0 = sBa[lane], bav1 = sBa[lane + 32];
    const float bbv0 = sBb[lane], bbv1 = sBb[lane + 32];
    const float* a0p = sAT + lane * 68;
    const float* a1p = sAT + (lane + 32) * 68;
    const float* b0p = sBT + lane * 68;
    const float* b1p = sBT + (lane + 32) * 68;
    const int stride = gridDim.x * 16;

    for (int g = blockIdx.x * 16 + warp; g < NN / 4; g += stride) {
        int n0 = g * 4;
        float4* av = (float4*)(g_agg + (size_t)n0 * 64);
        float4 z = make_float4(0.f, 0.f, 0.f, 0.f);
        float4 t0 = av[lane], t1v = av[lane + 32];
        ((float4*)scrN)[lane] = t0; ((float4*)scrN)[lane + 32] = t1v;
        av[lane] = z; av[lane + 32] = z;
        __syncwarp();
        u64 aa[4][2];
#pragma unroll
        for (int i = 0; i < 4; i++) { aa[i][0] = pack2(bav0, 0.f); aa[i][1] = pack2(bav1, 0.f); }
#pragma unroll 4
        for (int k = 0; k < 64; k += 4) {
            ulonglong2 w0 = *(const ulonglong2*)(a0p + k);
            ulonglong2 w1 = *(const ulonglong2*)(a1p + k);
#pragma unroll
            for (int i = 0; i < 4; i++) {
                ulonglong2 tt = *(const ulonglong2*)(scrN + i * 64 + k);
                fma2(aa[i][0], tt.x, w0.x); fma2(aa[i][0], tt.y, w0.y);
                fma2(aa[i][1], tt.x, w1.x); fma2(aa[i][1], tt.y, w1.y);
            }
        }
        __syncwarp();
#pragma unroll
        for (int i = 0; i < 4; i++) {
            scrN[i * 64 + lane]      = ssp_f(hsum2(aa[i][0]));
            scrN[i * 64 + lane + 32] = ssp_f(hsum2(aa[i][1]));
        }
        __syncwarp();
        u64 oo[4][2];
#pragma unroll
        for (int i = 0; i < 4; i++) { oo[i][0] = pack2(bbv0, 0.f); oo[i][1] = pack2(bbv1, 0.f); }
#pragma unroll 4
        for (int k = 0; k < 64; k += 4) {
            ulonglong2 w0 = *(const ulonglong2*)(b0p + k);
            ulonglong2 w1 = *(const ulonglong2*)(b1p + k);
#pragma unroll
            for (int i = 0; i < 4; i++) {
                ulonglong2 tt = *(const ulonglong2*)(scrN + i * 64 + k);
                fma2(oo[i][0], tt.x, w0.x); fma2(oo[i][0], tt.y, w0.y);
                fma2(oo[i][1], tt.x, w1.x); fma2(oo[i][1], tt.y, w1.y);
            }
        }
        __syncwarp();
#pragma unroll
        for (int i = 0; i < 4; i++) {
            float* hp = g_h + (size_t)(n0 + i) * 64;
            float h0 = hp[lane]      + hsum2(oo[i][0]);
            float h1 = hp[lane + 32] + hsum2(oo[i][1]);
            hp[lane] = h0; hp[lane + 32] = h1;
            scrN[i * 64 + lane] = h0; scrN[i * 64 + lane + 32] = h1;
        }
        __syncwarp();
        if (write_bf) {
            // refresh g_hbf for the 4 nodes: 64 slot-tasks, 2 per lane
#pragma unroll
            for (int rep = 0; rep < 2; rep++) {
                int task = 2 * lane + rep;
                int node = task >> 4, s = task & 15;
                int kt = s >> 2, qq = s & 3;
                int k1 = 16 * kt + 2 * qq;
                const float* hp = scrN + node * 64;
                uint32_t h0, l0, h1, l1;
                bfsplit2(hp[k1],     hp[k1 + 1], h0, l0);
                bfsplit2(hp[k1 + 8], hp[k1 + 9], h1, l1);
                g_hbf[(size_t)(n0 + node) * 32 + s]      = make_uint2(h0, h1);
                g_hbf[(size_t)(n0 + node) * 32 + 16 + s] = make_uint2(l0, l1);
            }
        }
        __syncwarp();
    }
}

// ---------------- readout + per-graph mean ----------------
__global__ void __launch_bounds__(256) k_readout(
    const int* __restrict__ gid,
    const float* __restrict__ d1w, const float* __restrict__ d1b,
    const float* __restrict__ d2w, const float* __restrict__ d2b)
{
    __shared__ float sW[2048], sB1r[32], sW2r[32];
    __shared__ float sB2r;
    int tid = threadIdx.x;
    for (int i = tid; i < 2048; i += 256) sW[i] = d1w[i];
    if (tid < 32) { sB1r[tid] = d1b[tid]; sW2r[tid] = d2w[tid]; }
    if (tid == 0) sB2r = d2b[0];
    __syncthreads();
    int lane = tid & 31, warp = tid >> 5;
    int nw = gridDim.x * 8;
    for (int n = blockIdx.x * 8 + warp; n < NN; n += nw) {
        float2 hv = *(const float2*)(g_h + (size_t)n * 64 + 2 * lane);
        float a = sB1r[lane];
#pragma unroll 8
        for (int k = 0; k < 64; k++) {
            float ek = __shfl_sync(0xffffffffu, (k & 1) ? hv.y : hv.x, k >> 1);
            a = fmaf(ek, sW[k * 32 + lane], a);
        }
        float p = ssp_f(a) * sW2r[lane];
#pragma unroll
        for (int off = 16; off; off >>= 1) p += __shfl_xor_sync(0xffffffffu, p, off);
        if (lane == 0) {
            int g = gid[n];
            atomicAdd(&g_sums[g], p + sB2r);
            atomicAdd(&g_cnt[g], 1.0f);
        }
    }
}

__global__ void k_final(float* __restrict__ out) {
    int t = threadIdx.x;
    if (t < NG) out[t] = g_sums[t] / fmaxf(g_cnt[t], 1.0f);
}

// ---------------- launch ----------------
extern "C" void kernel_launch(void* const* d_in, const int* in_sizes, int n_in,
                              void* d_out, int out_size) {
    const int*   az     = (const int*)d_in[0];
    const float* dist   = (const float*)d_in[1];
    const int*   src    = (const int*)d_in[2];
    const int*   dst    = (const int*)d_in[3];
    const int*   gid    = (const int*)d_in[4];
    const float* emb    = (const float*)d_in[5];
    const float* eu_w1  = (const float*)d_in[6];
    const float* eu_b1  = (const float*)d_in[7];
    const float* eu_w2  = (const float*)d_in[8];
    const float* eu_b2  = (const float*)d_in[9];
    const float* pe1_w  = (const float*)d_in[10];
    const float* pe1_b  = (const float*)d_in[11];
    const float* pe2_w  = (const float*)d_in[12];
    const float* pe2_b  = (const float*)d_in[13];
    const float* pn2a_w = (const float*)d_in[14];
    const float* pn2a_b = (const float*)d_in[15];
    const float* pn2b_w = (const float*)d_in[16];
    const float* pn2b_b = (const float*)d_in[17];
    const float* d1w    = (const float*)d_in[18];
    const float* d1b    = (const float*)d_in[19];
    const float* d2w    = (const float*)d_in[20];
    const float* d2b    = (const float*)d_in[21];

    cudaFuncSetAttribute(k_edge_mma, cudaFuncAttributeMaxDynamicSharedMemorySize, EDGE_SMEM);
    cudaFuncSetAttribute(k_update,   cudaFuncAttributeMaxDynamicSharedMemorySize, UPD_SMEM_FLOATS * 4);

    k_init_nodes<<<(NN * 16 + 255) / 256, 256>>>(az, emb);
    k_h2bf<<<(NN * 16 + 255) / 256, 256>>>();
    k_init_edges<<<(NE * 16 + 255) / 256, 256>>>(dist);
    k_zero_pool<<<1, 256>>>();
    k_prep<<<(3 * 10240 + 255) / 256, 256>>>(eu_w1, eu_w2, pe1_w, pe2_w);

    for (int l = 0; l < 3; l++) {
        k_edge_mma<<<148, 384, EDGE_SMEM>>>(
            l, (l < 2) ? 1 : 0, src, dst,
            eu_b1 + l * 128, eu_b2 + l * 64,
            pe1_b + l * 64,  pe2_b + l * 64);
        k_update<<<148, 512, UPD_SMEM_FLOATS * 4>>>(
            pn2a_w + (size_t)l * 4096, pn2a_b + l * 64,
            pn2b_w + (size_t)l * 4096, pn2b_b + l * 64,
            (l < 2) ? 1 : 0);
    }
    k_readout<<<296, 256>>>(gid, d1w, d1b, d2w, d2b);
    k_final<<<1, 256>>>((float*)d_out);
}

// round 9
// speedup vs baseline: 1.8220x; 1.0758x over previous
#include <cuda_runtime.h>
#include <cuda_bf16.h>
#include <math.h>
#include <stdint.h>

#define NN 50000
#define NE 800000
#define NG 256
#define LN2F 0.69314718055994531f

// ---------------- scratch (device globals) ----------------
__device__ float g_h  [NN * 64];
__device__ float g_agg[NN * 64];
__device__ float g_sums[NG];
__device__ float g_cnt [NG];
// split-planar bf16 activations, A-fragment slot layout:
//   per row: 16 hi u64 slots + 16 lo u64 slots (256B).
//   slot s = 4*kt + q  holds bf16x2 pairs for cols (16kt+2q, +1) [.x] and (16kt+2q+8, +9) [.y]
__device__ uint2 g_ebf[(size_t)NE * 32];
__device__ uint2 g_hbf[(size_t)NN * 32];
// pre-packed B fragments: 3 layers x 320 frags x 32 lanes (uint4 = {bh01,bh23,bl01,bl23})
__device__ uint4 g_frags[3 * 10240];

typedef unsigned long long u64;

__device__ __forceinline__ u64 pack2(float lo, float hi) {
    u64 r; asm("mov.b64 %0, {%1, %2};" : "=l"(r) : "f"(lo), "f"(hi)); return r;
}
__device__ __forceinline__ void fma2(u64 &d, u64 a, u64 b) {
    asm("fma.rn.f32x2 %0, %1, %2, %0;" : "+l"(d) : "l"(a), "l"(b));
}
__device__ __forceinline__ float hsum2(u64 v) {
    float lo, hi; asm("mov.b64 {%0, %1}, %2;" : "=f"(lo), "=f"(hi) : "l"(v));
    return lo + hi;
}
__device__ __forceinline__ float ssp_f(float x) {
    return fmaxf(x, 0.0f) + __logf(1.0f + __expf(-fabsf(x))) - LN2F;
}
// split two floats into bf16 hi pair + bf16 lo (residual) pair, packed b32 (first arg low half)
__device__ __forceinline__ void bfsplit2(float a, float b, uint32_t &hi, uint32_t &lo) {
    __nv_bfloat16 ha = __float2bfloat16_rn(a), hb = __float2bfloat16_rn(b);
    hi = (uint32_t)__bfloat16_as_ushort(ha) | ((uint32_t)__bfloat16_as_ushort(hb) << 16);
    __nv_bfloat16 la = __float2bfloat16_rn(a - __bfloat162float(ha));
    __nv_bfloat16 lb = __float2bfloat16_rn(b - __bfloat162float(hb));
    lo = (uint32_t)__bfloat16_as_ushort(la) | ((uint32_t)__bfloat16_as_ushort(lb) << 16);
}

__device__ __forceinline__ void mma_bf16(float* c,
    uint32_t a0, uint32_t a1, uint32_t a2, uint32_t a3, uint32_t b0, uint32_t b1) {
    asm("mma.sync.aligned.m16n8k16.row.col.f32.bf16.bf16.f32 "
        "{%0,%1,%2,%3}, {%4,%5,%6,%7}, {%8,%9}, {%0,%1,%2,%3};"
        : "+f"(c[0]), "+f"(c[1]), "+f"(c[2]), "+f"(c[3])
        : "r"(a0), "r"(a1), "r"(a2), "r"(a3), "r"(b0), "r"(b1));
}

// ---------------- fused weight-fragment prep + pool zero (launch idx 0) ----------------
__global__ void k_prep_zero(const float* __restrict__ eu_w1, const float* __restrict__ eu_w2,
                            const float* __restrict__ pe1_w, const float* __restrict__ pe2_w) {
    int s = blockIdx.x * blockDim.x + threadIdx.x;
    if (s < NG) { g_sums[s] = 0.f; g_cnt[s] = 0.f; }
    if (s >= 3 * 10240) return;
    int l = s / 10240, r = s % 10240;
    int f = r >> 5, lane = r & 31;
    const float* W; int NT, N, fl;
    if (f < 192)      { W = eu_w1 + (size_t)l * 24576; fl = f;       NT = 16; N = 128; }
    else if (f < 256) { W = eu_w2 + (size_t)l * 8192;  fl = f - 192; NT = 8;  N = 64; }
    else if (f < 288) { W = pe1_w + (size_t)l * 4096;  fl = f - 256; NT = 8;  N = 64; }
    else              { W = pe2_w + (size_t)l * 4096;  fl = f - 288; NT = 8;  N = 64; }
    int nt = fl % NT, kst = fl / NT;
    int n  = nt * 8 + (lane >> 2);
    int k0 = kst * 16 + 2 * (lane & 3);
    float w0 = W[(size_t)k0 * N + n];
    float w1 = W[(size_t)(k0 + 1) * N + n];
    float w2 = W[(size_t)(k0 + 8) * N + n];
    float w3 = W[(size_t)(k0 + 9) * N + n];
    uint32_t h01, l01, h23, l23;
    bfsplit2(w0, w1, h01, l01);
    bfsplit2(w2, w3, h23, l23);
    g_frags[s] = make_uint4(h01, h23, l01, l23);
}

// ---------------- fused node init: g_h + g_hbf + agg zero (launch idx 1) ----------------
__global__ void k_init_nodes_bf(const int* __restrict__ az, const float* __restrict__ emb) {
    int t = blockIdx.x * blockDim.x + threadIdx.x;
    if (t >= NN * 16) return;
    int n = t >> 4, s = t & 15;
    int z = __ldg(az + n);
    int kt = s >> 2, q = s & 3;
    int k1 = 16 * kt + 2 * q;
    const float* ep = emb + (size_t)z * 64;
    float e0 = __ldg(ep + k1), e1 = __ldg(ep + k1 + 1);
    float e8 = __ldg(ep + k1 + 8), e9 = __ldg(ep + k1 + 9);
    float* hp = g_h + (size_t)n * 64;
    hp[k1] = e0; hp[k1 + 1] = e1; hp[k1 + 8] = e8; hp[k1 + 9] = e9;
    uint32_t h0, l0, h1, l1;
    bfsplit2(e0, e1, h0, l0);
    bfsplit2(e8, e9, h1, l1);
    g_hbf[(size_t)n * 32 + s]      = make_uint2(h0, h1);
    g_hbf[(size_t)n * 32 + 16 + s] = make_uint2(l0, l1);
    ((float4*)(g_agg + (size_t)n * 64))[s] = make_float4(0.f, 0.f, 0.f, 0.f);
}

// ---------------- edge RBF init (launch idx 2) ----------------
__global__ void k_init_edges(const float* __restrict__ dist) {
    int t = blockIdx.x * blockDim.x + threadIdx.x;
    if (t >= NE * 16) return;
    int e = t >> 4, s = t & 15;
    int kt = s >> 2, q = s & 3;
    int k1 = 16 * kt + 2 * q;
    float d = dist[e];
    const float gap = 63.0f / 5.0f, step = 5.0f / 63.0f;
    float v0, v1, v2, v3;
    { float df = d - step * (float)(k1);     v0 = __expf(-df * df * gap); }
    { float df = d - step * (float)(k1 + 1); v1 = __expf(-df * df * gap); }
    { float df = d - step * (float)(k1 + 8); v2 = __expf(-df * df * gap); }
    { float df = d - step * (float)(k1 + 9); v3 = __expf(-df * df * gap); }
    uint32_t h0, l0, h1, l1;
    bfsplit2(v0, v1, h0, l0);
    bfsplit2(v2, v3, h1, l1);
    g_ebf[(size_t)e * 32 + s]      = make_uint2(h0, h1);
    g_ebf[(size_t)e * 32 + 16 + s] = make_uint2(l0, l1);
}

// ---------------- smem layout for k_edge_mma ----------------
#define FRAG_U4   10240                 // 320 frags * 32 lanes
#define SM_BIAS1  (FRAG_U4 * 16)        // 163840 B : b1[128]
#define SM_BIAS2  (SM_BIAS1 + 512)      // b2[64]
#define SM_Q1     (SM_BIAS2 + 256)      // q1[64]
#define SM_Q2     (SM_Q1 + 256)         // q2[64]
#define EDGE_SMEM (SM_Q2 + 256)         // 165120 B

#define FR1 0
#define FR2 (192 * 32)
#define FR3 (256 * 32)
#define FR4 (288 * 32)

// ---------------- the mma.sync edge kernel (M=16/warp, 384 thr, pipelined gathers) ----------------
__global__ void __launch_bounds__(384, 1) k_edge_mma(
    int layer, int store_e,
    const int* __restrict__ src, const int* __restrict__ dst,
    const float* __restrict__ b1, const float* __restrict__ b2,
    const float* __restrict__ pb1, const float* __restrict__ pb2)
{
    extern __shared__ char smem[];
    uint4* sm4 = (uint4*)smem;
    const int tid = threadIdx.x;

    // load weight fragments + biases
    {
        const uint4* srcf = g_frags + (size_t)layer * FRAG_U4;
        for (int i = tid; i < FRAG_U4; i += 384) sm4[i] = srcf[i];
        float* sB1 = (float*)(smem + SM_BIAS1);
        float* sB2 = (float*)(smem + SM_BIAS2);
        float* sQ1 = (float*)(smem + SM_Q1);
        float* sQ2 = (float*)(smem + SM_Q2);
        if (tid < 128) sB1[tid] = b1[tid];
        if (tid < 64) { sB2[tid] = b2[tid]; sQ1[tid] = pb1[tid]; sQ2[tid] = pb2[tid]; }
    }
    __syncthreads();

    const float* sB1f = (const float*)(smem + SM_BIAS1);
    const float* sB2f = (const float*)(smem + SM_BIAS2);
    const float* sQ1f = (const float*)(smem + SM_Q1);
    const float* sQ2f = (const float*)(smem + SM_Q2);

    const int wid = tid >> 5, lane = tid & 31;
    const int gr = lane >> 2;            // row group 0..7
    const int q  = lane & 3;
    const int t2 = 2 * q;                // col pair base

    const int NTILES = NE / 16;          // 50000
    const int wstride = gridDim.x * 12;

    int tile = blockIdx.x * 12 + wid;
    // index prefetch (one tile ahead)
    int pis0 = 0, pis8 = 0, pid0 = 0, pid8 = 0;
    if (tile < NTILES) {
        pis0 = __ldg(src + tile * 16 + gr);      pis8 = __ldg(src + tile * 16 + gr + 8);
        pid0 = __ldg(dst + tile * 16 + gr);      pid8 = __ldg(dst + tile * 16 + gr + 8);
    }

    for (; tile < NTILES; tile += wstride) {
        const int base = tile * 16;
        const int r0 = base + gr, r1 = base + gr + 8;
        const int is0 = pis0, is8 = pis8, id0 = pid0, id8 = pid8;
        {   // prefetch next tile's indices
            int tn = tile + wstride;
            if (tn < NTILES) {
                pis0 = __ldg(src + tn * 16 + gr); pis8 = __ldg(src + tn * 16 + gr + 8);
                pid0 = __ldg(dst + tn * 16 + gr); pid8 = __ldg(dst + tn * 16 + gr + 8);
            }
        }

        const uint2* PA[3] = { g_hbf + (size_t)is0 * 32, g_hbf + (size_t)id0 * 32, g_ebf + (size_t)r0 * 32 };
        const uint2* PB[3] = { g_hbf + (size_t)is8 * 32, g_hbf + (size_t)id8 * 32, g_ebf + (size_t)r1 * 32 };

        // ============ stage 1: C1[16x128] = [hsrc|hdst|e] @ W1 (pipelined) ============
        float c1[16][4];
#pragma unroll
        for (int nt = 0; nt < 16; nt++) { c1[nt][0] = c1[nt][1] = c1[nt][2] = c1[nt][3] = 0.f; }

        uint2 bh0[2], bh1[2], bl0[2], bl1[2];
        bh0[0] = __ldg(PA[0] + q);      bh1[0] = __ldg(PB[0] + q);
        bl0[0] = __ldg(PA[0] + 16 + q); bl1[0] = __ldg(PB[0] + 16 + q);
#pragma unroll
        for (int g = 0; g < 12; g++) {
            const int cb = g & 1, nb = cb ^ 1;
            if (g < 11) {
                const int gn = g + 1, mt = gn >> 2, kt2 = gn & 3;
                bh0[nb] = __ldg(PA[mt] + 4 * kt2 + q);      bh1[nb] = __ldg(PB[mt] + 4 * kt2 + q);
                bl0[nb] = __ldg(PA[mt] + 16 + 4 * kt2 + q); bl1[nb] = __ldg(PB[mt] + 16 + 4 * kt2 + q);
            }
            const uint4* fp = sm4 + FR1 + (size_t)g * 16 * 32 + lane;
#pragma unroll
            for (int nt = 0; nt < 16; nt++) {
                uint4 f = fp[nt * 32];
                mma_bf16(c1[nt], bh0[cb].x, bh1[cb].x, bh0[cb].y, bh1[cb].y, f.x, f.y);
                mma_bf16(c1[nt], bl0[cb].x, bl1[cb].x, bl0[cb].y, bl1[cb].y, f.x, f.y);
                mma_bf16(c1[nt], bh0[cb].x, bh1[cb].x, bh0[cb].y, bh1[cb].y, f.z, f.w);
            }
        }

        // ============ epi1+stage2 interleaved per kt: C2 = ssp(C1+b1) @ W2 ============
        float c2[8][4];
#pragma unroll
        for (int nt = 0; nt < 8; nt++) { c2[nt][0] = c2[nt][1] = c2[nt][2] = c2[nt][3] = 0.f; }
#pragma unroll 1
        for (int kt = 0; kt < 8; kt++) {
            uint32_t a2h[4], a2l[4];
#pragma unroll
            for (int half = 0; half < 2; half++) {
                int nt = 2 * kt + half;
                float2 bb = *(const float2*)(sB1f + nt * 8 + t2);
                float v0 = ssp_f(c1[nt][0] + bb.x), v1 = ssp_f(c1[nt][1] + bb.y);
                float v2 = ssp_f(c1[nt][2] + bb.x), v3 = ssp_f(c1[nt][3] + bb.y);
                bfsplit2(v0, v1, a2h[2 * half],     a2l[2 * half]);
                bfsplit2(v2, v3, a2h[2 * half + 1], a2l[2 * half + 1]);
            }
            const uint4* fp = sm4 + FR2 + (size_t)kt * 8 * 32 + lane;
#pragma unroll
            for (int nt = 0; nt < 8; nt++) {
                uint4 f = fp[nt * 32];
                mma_bf16(c2[nt], a2h[0], a2h[1], a2h[2], a2h[3], f.x, f.y);
                mma_bf16(c2[nt], a2l[0], a2l[1], a2l[2], a2l[3], f.x, f.y);
                mma_bf16(c2[nt], a2h[0], a2h[1], a2h[2], a2h[3], f.z, f.w);
            }
        }

        // ============ epi2+stage3 interleaved: C3 = (C2+b2) @ P1 ; e' -> g_ebf ============
        float c3[8][4];
#pragma unroll
        for (int nt = 0; nt < 8; nt++) { c3[nt][0] = c3[nt][1] = c3[nt][2] = c3[nt][3] = 0.f; }
#pragma unroll 1
        for (int kt = 0; kt < 4; kt++) {
            uint32_t a3h[4], a3l[4];
#pragma unroll
            for (int half = 0; half < 2; half++) {
                int nt = 2 * kt + half;
                float2 bb = *(const float2*)(sB2f + nt * 8 + t2);
                float x0 = c2[nt][0] + bb.x, x1 = c2[nt][1] + bb.y;
                float x2 = c2[nt][2] + bb.x, x3 = c2[nt][3] + bb.y;
                bfsplit2(x0, x1, a3h[2 * half],     a3l[2 * half]);
                bfsplit2(x2, x3, a3h[2 * half + 1], a3l[2 * half + 1]);
            }
            if (store_e) {
                uint2* pe0 = g_ebf + (size_t)r0 * 32;
                uint2* pe1 = g_ebf + (size_t)r1 * 32;
                pe0[4 * kt + q]      = make_uint2(a3h[0], a3h[2]);
                pe1[4 * kt + q]      = make_uint2(a3h[1], a3h[3]);
                pe0[16 + 4 * kt + q] = make_uint2(a3l[0], a3l[2]);
                pe1[16 + 4 * kt + q] = make_uint2(a3l[1], a3l[3]);
            }
            const uint4* fp = sm4 + FR3 + (size_t)kt * 8 * 32 + lane;
#pragma unroll
            for (int nt = 0; nt < 8; nt++) {
                uint4 f = fp[nt * 32];
                mma_bf16(c3[nt], a3h[0], a3h[1], a3h[2], a3h[3], f.x, f.y);
                mma_bf16(c3[nt], a3l[0], a3l[1], a3l[2], a3l[3], f.x, f.y);
                mma_bf16(c3[nt], a3h[0], a3h[1], a3h[2], a3h[3], f.z, f.w);
            }
        }

        // ============ epi3+stage4 interleaved: C4 = ssp(C3+q1) @ P2 ============
        float c4[8][4];
#pragma unroll
        for (int nt = 0; nt < 8; nt++) { c4[nt][0] = c4[nt][1] = c4[nt][2] = c4[nt][3] = 0.f; }
#pragma unroll 1
        for (int kt = 0; kt < 4; kt++) {
            uint32_t a4h[4], a4l[4];
#pragma unroll
            for (int half = 0; half < 2; half++) {
                int nt = 2 * kt + half;
                float2 bb = *(const float2*)(sQ1f + nt * 8 + t2);
                float v0 = ssp_f(c3[nt][0] + bb.x), v1 = ssp_f(c3[nt][1] + bb.y);
                float v2 = ssp_f(c3[nt][2] + bb.x), v3 = ssp_f(c3[nt][3] + bb.y);
                bfsplit2(v0, v1, a4h[2 * half],     a4l[2 * half]);
                bfsplit2(v2, v3, a4h[2 * half + 1], a4l[2 * half + 1]);
            }
            const uint4* fp = sm4 + FR4 + (size_t)kt * 8 * 32 + lane;
#pragma unroll
            for (int nt = 0; nt < 8; nt++) {
                uint4 f = fp[nt * 32];
                mma_bf16(c4[nt], a4h[0], a4h[1], a4h[2], a4h[3], f.x, f.y);
                mma_bf16(c4[nt], a4l[0], a4l[1], a4l[2], a4l[3], f.x, f.y);
                mma_bf16(c4[nt], a4h[0], a4h[1], a4h[2], a4h[3], f.z, f.w);
            }
        }

        // ============ epi 4: he = C4 + q2; scatter-add to g_agg[dst] ============
        {
            float* da = g_agg + (size_t)id0 * 64;
            float* db = g_agg + (size_t)id8 * 64;
#pragma unroll
            for (int nt = 0; nt < 8; nt++) {
                float2 bb = *(const float2*)(sQ2f + nt * 8 + t2);
                float x0 = c4[nt][0] + bb.x, x1 = c4[nt][1] + bb.y;
                float x2 = c4[nt][2] + bb.x, x3 = c4[nt][3] + bb.y;
                asm volatile("red.global.add.v2.f32 [%0], {%1, %2};"
                             :: "l"(da + nt * 8 + t2), "f"(x0), "f"(x1) : "memory");
                asm volatile("red.global.add.v2.f32 [%0], {%1, %2};"
                             :: "l"(db + nt * 8 + t2), "f"(x2), "f"(x3) : "memory");
            }
        }
    }
}

// ---------------- node update: h += ssp(agg@A+ba)@B + bb; agg=0; refresh g_hbf ----------------
#define UPD_SMEM_FLOATS 12928
__global__ void __launch_bounds__(512, 1) k_update(
    const float* __restrict__ wa, const float* __restrict__ ba,
    const float* __restrict__ wb, const float* __restrict__ bb_,
    int write_bf)
{
    extern __shared__ float sm[];
    float* sAT = sm;
    float* sBT = sm + 4352;
    float* sBa = sm + 8704;
    float* sBb = sm + 8768;
    float* sScr = sm + 8832;
    int tid = threadIdx.x;
    for (int i = tid; i < 4096; i += 512) {
        int k = i >> 6, c = i & 63;
        sAT[c * 68 + k] = wa[i];
        sBT[c * 68 + k] = wb[i];
    }
    if (tid < 64) { sBa[tid] = ba[tid]; sBb[tid] = bb_[tid]; }
    __syncthreads();

    int lane = tid & 31, warp = tid >> 5;
    float* scrN = sScr + warp * 256;
    const float bav0 = sBa[lane], bav1 = sBa[lane + 32];
    const float bbv0 = sBb[lane], bbv1 = sBb[lane + 32];
    const float* a0p = sAT + lane * 68;
    const float* a1p = sAT + (lane + 32) * 68;
    const float* b0p = sBT + lane * 68;
    const float* b1p = sBT + (lane + 32) * 68;
    const int stride = gridDim.x * 16;

    for (int g = blockIdx.x * 16 + warp; g < NN / 4; g += stride) {
        int n0 = g * 4;
        float4* av = (float4*)(g_agg + (size_t)n0 * 64);
        float4 z = make_float4(0.f, 0.f, 0.f, 0.f);
        float4 t0 = av[lane], t1v = av[lane + 32];
        ((float4*)scrN)[lane] = t0; ((float4*)scrN)[lane + 32] = t1v;
        av[lane] = z; av[lane + 32] = z;
        __syncwarp();
        u64 aa[4][2];
#pragma unroll
        for (int i = 0; i < 4; i++) { aa[i][0] = pack2(bav0, 0.f); aa[i][1] = pack2(bav1, 0.f); }
#pragma unroll 4
        for (int k = 0; k < 64; k += 4) {
            ulonglong2 w0 = *(const ulonglong2*)(a0p + k);
            ulonglong2 w1 = *(const ulonglong2*)(a1p + k);
#pragma unroll
            for (int i = 0; i < 4; i++) {
                ulonglong2 tt = *(const ulonglong2*)(scrN + i * 64 + k);
                fma2(aa[i][0], tt.x, w0.x); fma2(aa[i][0], tt.y, w0.y);
                fma2(aa[i][1], tt.x, w1.x); fma2(aa[i][1], tt.y, w1.y);
            }
        }
        __syncwarp();
#pragma unroll
        for (int i = 0; i < 4; i++) {
            scrN[i * 64 + lane]      = ssp_f(hsum2(aa[i][0]));
            scrN[i * 64 + lane + 32] = ssp_f(hsum2(aa[i][1]));
        }
        __syncwarp();
        u64 oo[4][2];
#pragma unroll
        for (int i = 0; i < 4; i++) { oo[i][0] = pack2(bbv0, 0.f); oo[i][1] = pack2(bbv1, 0.f); }
#pragma unroll 4
        for (int k = 0; k < 64; k += 4) {
            ulonglong2 w0 = *(const ulonglong2*)(b0p + k);
            ulonglong2 w1 = *(const ulonglong2*)(b1p + k);
#pragma unroll
            for (int i = 0; i < 4; i++) {
                ulonglong2 tt = *(const ulonglong2*)(scrN + i * 64 + k);
                fma2(oo[i][0], tt.x, w0.x); fma2(oo[i][0], tt.y, w0.y);
                fma2(oo[i][1], tt.x, w1.x); fma2(oo[i][1], tt.y, w1.y);
            }
        }
        __syncwarp();
#pragma unroll
        for (int i = 0; i < 4; i++) {
            float* hp = g_h + (size_t)(n0 + i) * 64;
            float h0 = hp[lane]      + hsum2(oo[i][0]);
            float h1 = hp[lane + 32] + hsum2(oo[i][1]);
            hp[lane] = h0; hp[lane + 32] = h1;
            scrN[i * 64 + lane] = h0; scrN[i * 64 + lane + 32] = h1;
        }
        __syncwarp();
        if (write_bf) {
#pragma unroll
            for (int rep = 0; rep < 2; rep++) {
                int task = 2 * lane + rep;
                int node = task >> 4, s = task & 15;
                int kt = s >> 2, qq = s & 3;
                int k1 = 16 * kt + 2 * qq;
                const float* hp = scrN + node * 64;
                uint32_t h0, l0, h1, l1;
                bfsplit2(hp[k1],     hp[k1 + 1], h0, l0);
                bfsplit2(hp[k1 + 8], hp[k1 + 9], h1, l1);
                g_hbf[(size_t)(n0 + node) * 32 + s]      = make_uint2(h0, h1);
                g_hbf[(size_t)(n0 + node) * 32 + 16 + s] = make_uint2(l0, l1);
            }
        }
        __syncwarp();
    }
}

// ---------------- readout + per-graph mean ----------------
__global__ void __launch_bounds__(256) k_readout(
    const int* __restrict__ gid,
    const float* __restrict__ d1w, const float* __restrict__ d1b,
    const float* __restrict__ d2w, const float* __restrict__ d2b)
{
    __shared__ float sW[2048], sB1r[32], sW2r[32];
    __shared__ float sB2r;
    int tid = threadIdx.x;
    for (int i = tid; i < 2048; i += 256) sW[i] = d1w[i];
    if (tid < 32) { sB1r[tid] = d1b[tid]; sW2r[tid] = d2w[tid]; }
    if (tid == 0) sB2r = d2b[0];
    __syncthreads();
    int lane = tid & 31, warp = tid >> 5;
    int nw = gridDim.x * 8;
    for (int n = blockIdx.x * 8 + warp; n < NN; n += nw) {
        float2 hv = *(const float2*)(g_h + (size_t)n * 64 + 2 * lane);
        float a = sB1r[lane];
#pragma unroll 8
        for (int k = 0; k < 64; k++) {
            float ek = __shfl_sync(0xffffffffu, (k & 1) ? hv.y : hv.x, k >> 1);
            a = fmaf(ek, sW[k * 32 + lane], a);
        }
        float p = ssp_f(a) * sW2r[lane];
#pragma unroll
        for (int off = 16; off; off >>= 1) p += __shfl_xor_sync(0xffffffffu, p, off);
        if (lane == 0) {
            int g = gid[n];
            atomicAdd(&g_sums[g], p + sB2r);
            atomicAdd(&g_cnt[g], 1.0f);
        }
    }
}

__global__ void k_final(float* __restrict__ out) {
    int t = threadIdx.x;
    if (t < NG) out[t] = g_sums[t] / fmaxf(g_cnt[t], 1.0f);
}

// ---------------- launch ----------------
extern "C" void kernel_launch(void* const* d_in, const int* in_sizes, int n_in,
                              void* d_out, int out_size) {
    const int*   az     = (const int*)d_in[0];
    const float* dist   = (const float*)d_in[1];
    const int*   src    = (const int*)d_in[2];
    const int*   dst    = (const int*)d_in[3];
    const int*   gid    = (const int*)d_in[4];
    const float* emb    = (const float*)d_in[5];
    const float* eu_w1  = (const float*)d_in[6];
    const float* eu_b1  = (const float*)d_in[7];
    const float* eu_w2  = (const float*)d_in[8];
    const float* eu_b2  = (const float*)d_in[9];
    const float* pe1_w  = (const float*)d_in[10];
    const float* pe1_b  = (const float*)d_in[11];
    const float* pe2_w  = (const float*)d_in[12];
    const float* pe2_b  = (const float*)d_in[13];
    const float* pn2a_w = (const float*)d_in[14];
    const float* pn2a_b = (const float*)d_in[15];
    const float* pn2b_w = (const float*)d_in[16];
    const float* pn2b_b = (const float*)d_in[17];
    const float* d1w    = (const float*)d_in[18];
    const float* d1b    = (const float*)d_in[19];
    const float* d2w    = (const float*)d_in[20];
    const float* d2b    = (const float*)d_in[21];

    cudaFuncSetAttribute(k_edge_mma, cudaFuncAttributeMaxDynamicSharedMemorySize, EDGE_SMEM);
    cudaFuncSetAttribute(k_update,   cudaFuncAttributeMaxDynamicSharedMemorySize, UPD_SMEM_FLOATS * 4);

    // launch order chosen so k_edge_mma is launch index 3 (ncu captures idx 3)
    k_prep_zero<<<120, 256>>>(eu_w1, eu_w2, pe1_w, pe2_w);           // idx 0
    k_init_nodes_bf<<<(NN * 16 + 255) / 256, 256>>>(az, emb);        // idx 1
    k_init_edges<<<(NE * 16 + 255) / 256, 256>>>(dist);              // idx 2

    for (int l = 0; l < 3; l++) {
        k_edge_mma<<<148, 384, EDGE_SMEM>>>(                          // idx 3 (l=0)
            l, (l < 2) ? 1 : 0, src, dst,
            eu_b1 + l * 128, eu_b2 + l * 64,
            pe1_b + l * 64,  pe2_b + l * 64);
        k_update<<<148, 512, UPD_SMEM_FLOATS * 4>>>(
            pn2a_w + (size_t)l * 4096, pn2a_b + l * 64,
            pn2b_w + (size_t)l * 4096, pn2b_b + l * 64,
            (l < 2) ? 1 : 0);
    }
    k_readout<<<296, 256>>>(gid, d1w, d1b, d2w, d2b);
    k_final<<<1, 256>>>((float*)d_out);
}